// round 4
// baseline (speedup 1.0000x reference)
#include <cuda_runtime.h>
#include <math.h>
#include <stdint.h>

#define Bb 64
#define LL 512
#define DD 512

// ----------------------------- scratch ---------------------------------------
__device__ float g_proj[(size_t)Bb * LL * DD];   // 64 MB (tf32-rounded fp32)
__device__ float g_wt[DD * DD];                  // W^T (tf32-rounded fp32)
__device__ float g_mt[Bb * LL];
__device__ float g_mf[Bb * LL];
__device__ float g_rowmax[Bb * LL];
__device__ float g_colmax[Bb * LL];
__device__ float g_alpha_t[Bb * LL];
__device__ float g_alpha_f[Bb * LL];
__device__ int   g_mask_fmt;

// ----------------------------- helpers ---------------------------------------
__device__ __forceinline__ uint32_t tf32r(float x) {
    float y;
    asm("cvt.rna.tf32.f32 %0, %1;" : "=f"(y) : "f"(x));
    return __float_as_uint(y);
}

__device__ __forceinline__ void mma_tf32(float* c, const uint32_t* a, const uint32_t* b) {
    asm volatile(
        "mma.sync.aligned.m16n8k8.row.col.f32.tf32.tf32.f32 "
        "{%0,%1,%2,%3}, {%4,%5,%6,%7}, {%8,%9}, {%0,%1,%2,%3};\n"
        : "+f"(c[0]), "+f"(c[1]), "+f"(c[2]), "+f"(c[3])
        : "r"(a[0]), "r"(a[1]), "r"(a[2]), "r"(a[3]), "r"(b[0]), "r"(b[1]));
}

__device__ __forceinline__ void atomicMaxF(float* a, float v) {
    if (v >= 0.0f) atomicMax((int*)a, __float_as_int(v));
    else           atomicMin((unsigned int*)a, __float_as_uint(v));
}

__device__ __forceinline__ float load_mask(const void* p, int i, int fmt) {
    if (fmt == 0) return ((const int*)p)[i] ? 1.0f : 0.0f;
    if (fmt == 1) return ((const float*)p)[i];
    return ((const unsigned char*)p)[i] ? 1.0f : 0.0f;
}

// ---- fragment-layout staging --------------------------------------------------
// A word layout: As[((row>>4)*2 + kk)*128 + phys*4 + s]
//   s = (row&15)>=8 ? 1:0  +  (k'>=4 ? 2:0), lane = (row&7)*4 + (k'&3),
//   phys = lane ^ (lane>>3). Read: uint4 = {a0,a1,a2,a3} for mma.
// B word layout: Bs[((row>>3)*2 + kk)*64 + phys*2 + s], s = (k'>=4).
//   Read: uint2 = {b0,b1}.
template <bool CVT>
__device__ __forceinline__ void stA(uint32_t* dst, int row, int kk, int q,
                                    float4 v, float m) {
    const int r15 = row & 15;
    const int s = (r15 >> 3) + ((q >> 2) << 1);
    const int base = (((row >> 4) * 2 + kk) << 7) + s;
    const int l0 = (r15 & 7) * 4;
    float a[4] = {v.x, v.y, v.z, v.w};
#pragma unroll
    for (int j = 0; j < 4; j++) {
        int lane = l0 + j;
        int phys = lane ^ (lane >> 3);
        dst[base + phys * 4] = CVT ? tf32r(a[j] * m) : __float_as_uint(a[j]);
    }
}

template <bool CVT>
__device__ __forceinline__ void stB(uint32_t* dst, int row, int kk, int q,
                                    float4 v, float m) {
    const int s = q >> 2;
    const int base = (((row >> 3) * 2 + kk) << 6) + s;
    const int l0 = (row & 7) * 4;
    float a[4] = {v.x, v.y, v.z, v.w};
#pragma unroll
    for (int j = 0; j < 4; j++) {
        int lane = l0 + j;
        int phys = lane ^ (lane >> 3);
        dst[base + phys * 2] = CVT ? tf32r(a[j] * m) : __float_as_uint(a[j]);
    }
}

// ----------------------------- small kernels ----------------------------------
__global__ void detect_kernel(const unsigned int* m) {
    int lane = threadIdx.x;
    bool i32 = true, f32 = true;
    for (int i = lane; i < 256; i += 32) {
        unsigned int w = m[i];
        i32 = i32 && (w <= 1u);
        f32 = f32 && (w == 0u || w == 0x3F800000u);
    }
    i32 = __all_sync(0xffffffffu, i32);
    f32 = __all_sync(0xffffffffu, f32);
    if (lane == 0) g_mask_fmt = i32 ? 0 : (f32 ? 1 : 2);
}

__global__ void prep_kernel(const void* mt, const void* mf) {
    int i = blockIdx.x * blockDim.x + threadIdx.x;
    if (i >= Bb * LL) return;
    int fmt = g_mask_fmt;
    g_mt[i] = load_mask(mt, i, fmt);
    g_mf[i] = load_mask(mf, i, fmt);
    float ninf = __int_as_float(0xff800000);
    g_rowmax[i] = ninf;
    g_colmax[i] = ninf;
}

__global__ void transpose_w(const float* __restrict__ W) {
    __shared__ float tile[32][33];
    int tx = threadIdx.x, ty = threadIdx.y;
    int x = blockIdx.x * 32 + tx;
    int y0 = blockIdx.y * 32;
#pragma unroll
    for (int j = 0; j < 32; j += 8)
        tile[ty + j][tx] = W[(size_t)(y0 + ty + j) * DD + x];
    __syncthreads();
    int xo = y0 + tx;
    int yo0 = blockIdx.x * 32;
#pragma unroll
    for (int j = 0; j < 32; j += 8)
        g_wt[(size_t)(yo0 + ty + j) * DD + xo] =
            __uint_as_float(tf32r(tile[tx][ty + j]));
}

// ----------------------------- tf32 mma GEMM -----------------------------------
// Both modes compute D[l,n] = sum_k A[l,k] * B[n,k]   (NT form)
// MODE 0: A = t (masked rows, cvt), B = g_wt (pre-rounded)  -> g_proj (rounded)
// MODE 1: A = g_proj (pre-rounded), B = f (masked, cvt)     -> row/col max only
#define BK 16

template <int MODE>
__global__ void __launch_bounds__(256, 2) mma_gemm(const float* __restrict__ Ag,
                                                   const float* __restrict__ Bg)
{
    __shared__ __align__(16) uint32_t As[2][2048];
    __shared__ __align__(16) uint32_t Bs[2][2048];
    __shared__ float s_rmax[128];
    __shared__ float s_cmax[128];

    const int tid  = threadIdx.x;
    const int lane = tid & 31;
    const int wid  = tid >> 5;
    const int wm   = wid & 1;     // 2 warps in M
    const int wn   = wid >> 1;    // 4 warps in N
    const int b  = blockIdx.z;
    const int l0 = blockIdx.y * 128;
    const int n0 = blockIdx.x * 128;

    const float* Aptr;
    const float* Bptr;
    float ma0 = 1.f, ma1 = 1.f, mb0 = 1.f, mb1 = 1.f;

    const int gr = tid >> 2;        // 0..63
    const int gc = (tid & 3) * 4;   // 0,4,8,12
    const int kkS = gc >> 3;        // staged kk
    const int qS  = gc & 7;         // 0 or 4

    if (MODE == 0) {
        Aptr = Ag + (size_t)b * LL * DD;
        Bptr = g_wt;
        ma0 = g_mt[b * LL + l0 + gr];
        ma1 = g_mt[b * LL + l0 + gr + 64];
    } else {
        Aptr = g_proj + (size_t)b * LL * DD;
        Bptr = Bg + (size_t)b * LL * DD;
        mb0 = g_mf[b * LL + n0 + gr];
        mb1 = g_mf[b * LL + n0 + gr + 64];
    }

    if (MODE == 1 && tid < 128) {
        s_rmax[tid] = __int_as_float(0xff800000);
        s_cmax[tid] = __int_as_float(0xff800000);
    }

    const float* Ab0 = Aptr + (size_t)(l0 + gr) * DD + gc;
    const float* Ab1 = Aptr + (size_t)(l0 + gr + 64) * DD + gc;
    const float* Bb0 = Bptr + (size_t)(n0 + gr) * DD + gc;
    const float* Bb1 = Bptr + (size_t)(n0 + gr + 64) * DD + gc;

    float acc[4][4][4];
#pragma unroll
    for (int i = 0; i < 4; i++)
#pragma unroll
        for (int j = 0; j < 4; j++)
#pragma unroll
            for (int q = 0; q < 4; q++) acc[i][j][q] = 0.0f;

    // ---- prologue: stage k-chunk 0 into buf 0
    {
        float4 va0 = *(const float4*)Ab0;
        float4 va1 = *(const float4*)Ab1;
        float4 vb0 = *(const float4*)Bb0;
        float4 vb1 = *(const float4*)Bb1;
        if (MODE == 0) {
            stA<true >(As[0], gr,      kkS, qS, va0, ma0);
            stA<true >(As[0], gr + 64, kkS, qS, va1, ma1);
            stB<false>(Bs[0], gr,      kkS, qS, vb0, 1.f);
            stB<false>(Bs[0], gr + 64, kkS, qS, vb1, 1.f);
        } else {
            stA<false>(As[0], gr,      kkS, qS, va0, 1.f);
            stA<false>(As[0], gr + 64, kkS, qS, va1, 1.f);
            stB<true >(Bs[0], gr,      kkS, qS, vb0, mb0);
            stB<true >(Bs[0], gr + 64, kkS, qS, vb1, mb1);
        }
    }
    __syncthreads();

    const int physL = lane ^ (lane >> 3);
    const int NKT = DD / BK;   // 32
    for (int kt = 0; kt < NKT; kt++) {
        const int buf = kt & 1;
        float4 va0, va1, vb0, vb1;
        if (kt + 1 < NKT) {
            const int K0 = (kt + 1) * BK;
            va0 = *(const float4*)(Ab0 + K0);
            va1 = *(const float4*)(Ab1 + K0);
            vb0 = *(const float4*)(Bb0 + K0);
            vb1 = *(const float4*)(Bb1 + K0);
        }

#pragma unroll
        for (int kk = 0; kk < 2; kk++) {
            uint4 af[4];
            uint2 bf[4];
#pragma unroll
            for (int mt = 0; mt < 4; mt++)
                af[mt] = *(const uint4*)&As[buf][(((wm * 4 + mt) * 2 + kk) << 7) + physL * 4];
#pragma unroll
            for (int nt = 0; nt < 4; nt++)
                bf[nt] = *(const uint2*)&Bs[buf][(((wn * 4 + nt) * 2 + kk) << 6) + physL * 2];
#pragma unroll
            for (int mt = 0; mt < 4; mt++)
#pragma unroll
                for (int nt = 0; nt < 4; nt++)
                    mma_tf32(acc[mt][nt], (const uint32_t*)&af[mt], (const uint32_t*)&bf[nt]);
        }

        if (kt + 1 < NKT) {
            const int nb = (kt + 1) & 1;
            if (MODE == 0) {
                stA<true >(As[nb], gr,      kkS, qS, va0, ma0);
                stA<true >(As[nb], gr + 64, kkS, qS, va1, ma1);
                stB<false>(Bs[nb], gr,      kkS, qS, vb0, 1.f);
                stB<false>(Bs[nb], gr + 64, kkS, qS, vb1, 1.f);
            } else {
                stA<false>(As[nb], gr,      kkS, qS, va0, 1.f);
                stA<false>(As[nb], gr + 64, kkS, qS, va1, 1.f);
                stB<true >(Bs[nb], gr,      kkS, qS, vb0, mb0);
                stB<true >(Bs[nb], gr + 64, kkS, qS, vb1, mb1);
            }
            __syncthreads();
        }
    }

    // ----------------------------- epilogue -------------------------------------
    if (MODE == 0) {
        float* Crow = g_proj + (size_t)b * LL * DD;
#pragma unroll
        for (int mt = 0; mt < 4; mt++) {
            const int r = l0 + wm * 64 + mt * 16 + (lane >> 2);
#pragma unroll
            for (int nt = 0; nt < 4; nt++) {
                const int c = n0 + wn * 32 + nt * 8 + 2 * (lane & 3);
                float2 o0, o1;
                o0.x = __uint_as_float(tf32r(acc[mt][nt][0]));
                o0.y = __uint_as_float(tf32r(acc[mt][nt][1]));
                o1.x = __uint_as_float(tf32r(acc[mt][nt][2]));
                o1.y = __uint_as_float(tf32r(acc[mt][nt][3]));
                *(float2*)(Crow + (size_t)r * DD + c)       = o0;
                *(float2*)(Crow + (size_t)(r + 8) * DD + c) = o1;
            }
        }
    } else {
        __syncthreads();
        const float NINF = __int_as_float(0xff800000);
#pragma unroll
        for (int mt = 0; mt < 4; mt++) {
#pragma unroll
            for (int h = 0; h < 2; h++) {
                float v = NINF;
#pragma unroll
                for (int nt = 0; nt < 4; nt++)
                    v = fmaxf(v, fmaxf(acc[mt][nt][2 * h], acc[mt][nt][2 * h + 1]));
                v = fmaxf(v, __shfl_xor_sync(0xffffffffu, v, 1));
                v = fmaxf(v, __shfl_xor_sync(0xffffffffu, v, 2));
                if ((lane & 3) == 0) {
                    int row = wm * 64 + mt * 16 + (lane >> 2) + h * 8;
                    atomicMaxF(&s_rmax[row], v);
                }
            }
        }
#pragma unroll
        for (int nt = 0; nt < 4; nt++) {
#pragma unroll
            for (int j = 0; j < 2; j++) {
                float v = NINF;
#pragma unroll
                for (int mt = 0; mt < 4; mt++)
                    v = fmaxf(v, fmaxf(acc[mt][nt][j], acc[mt][nt][2 + j]));
                v = fmaxf(v, __shfl_xor_sync(0xffffffffu, v, 4));
                v = fmaxf(v, __shfl_xor_sync(0xffffffffu, v, 8));
                v = fmaxf(v, __shfl_xor_sync(0xffffffffu, v, 16));
                if (lane < 4) {
                    int col = wn * 32 + nt * 8 + 2 * lane + j;
                    atomicMaxF(&s_cmax[col], v);
                }
            }
        }
        __syncthreads();
        if (tid < 128) {
            atomicMaxF(&g_rowmax[b * LL + l0 + tid], s_rmax[tid]);
            atomicMaxF(&g_colmax[b * LL + n0 + tid], s_cmax[tid]);
        }
    }
}

// ----------------------------- softmax ----------------------------------------
__global__ void softmax_kernel() {
    const int idx = blockIdx.x;
    const bool isF = idx >= Bb;
    const int b = isF ? idx - Bb : idx;
    const float* mx = isF ? (g_colmax + b * LL) : (g_rowmax + b * LL);
    const float* mk = isF ? (g_mf + b * LL) : (g_mt + b * LL);
    float* out = isF ? (g_alpha_f + b * LL) : (g_alpha_t + b * LL);

    const int tid = threadIdx.x;
    int i0 = tid, i1 = tid + 256;
    float m0v = mk[i0], m1v = mk[i1];
    float v0 = tanhf(mx[i0]) + (m0v - 1.0f) * 1000000.0f;
    float v1 = tanhf(mx[i1]) + (m1v - 1.0f) * 1000000.0f;

    __shared__ float red[256];
    red[tid] = fmaxf(v0, v1);
    __syncthreads();
    for (int s = 128; s > 0; s >>= 1) {
        if (tid < s) red[tid] = fmaxf(red[tid], red[tid + s]);
        __syncthreads();
    }
    float vm = red[0];
    __syncthreads();

    float e0 = expf(v0 - vm);
    float e1 = expf(v1 - vm);
    red[tid] = e0 + e1;
    __syncthreads();
    for (int s = 128; s > 0; s >>= 1) {
        if (tid < s) red[tid] += red[tid + s];
        __syncthreads();
    }
    float inv = 1.0f / red[0];
    out[i0] = e0 * inv * m0v;
    out[i1] = e1 * inv * m1v;
}

// ----------------------------- combine -----------------------------------------
__global__ void combine_kernel(const float* __restrict__ T,
                               const float* __restrict__ F,
                               float* __restrict__ out)
{
    const int b = blockIdx.y;
    const int d = blockIdx.x * 128 + threadIdx.x;
    const float* at = g_alpha_t + b * LL;
    const float* af = g_alpha_f + b * LL;
    const float* tp = T + (size_t)b * LL * DD + d;
    const float* fp = F + (size_t)b * LL * DD + d;

    float a0 = 0.f, a1 = 0.f, a2 = 0.f, a3 = 0.f;
    float c0 = 0.f, c1 = 0.f, c2 = 0.f, c3 = 0.f;
#pragma unroll 2
    for (int l = 0; l < LL; l += 8) {
        a0 = fmaf(at[l + 0], tp[(size_t)(l + 0) * DD], a0);
        a1 = fmaf(at[l + 1], tp[(size_t)(l + 1) * DD], a1);
        a2 = fmaf(at[l + 2], tp[(size_t)(l + 2) * DD], a2);
        a3 = fmaf(at[l + 3], tp[(size_t)(l + 3) * DD], a3);
        c0 = fmaf(at[l + 4], tp[(size_t)(l + 4) * DD], c0);
        c1 = fmaf(at[l + 5], tp[(size_t)(l + 5) * DD], c1);
        c2 = fmaf(at[l + 6], tp[(size_t)(l + 6) * DD], c2);
        c3 = fmaf(at[l + 7], tp[(size_t)(l + 7) * DD], c3);
    }
#pragma unroll 2
    for (int m = 0; m < LL; m += 8) {
        a0 = fmaf(af[m + 0], fp[(size_t)(m + 0) * DD], a0);
        a1 = fmaf(af[m + 1], fp[(size_t)(m + 1) * DD], a1);
        a2 = fmaf(af[m + 2], fp[(size_t)(m + 2) * DD], a2);
        a3 = fmaf(af[m + 3], fp[(size_t)(m + 3) * DD], a3);
        c0 = fmaf(af[m + 4], fp[(size_t)(m + 4) * DD], c0);
        c1 = fmaf(af[m + 5], fp[(size_t)(m + 5) * DD], c1);
        c2 = fmaf(af[m + 6], fp[(size_t)(m + 6) * DD], c2);
        c3 = fmaf(af[m + 7], fp[(size_t)(m + 7) * DD], c3);
    }
    out[b * DD + d] = ((a0 + a1) + (a2 + a3)) + ((c0 + c1) + (c2 + c3));
}

// ----------------------------- launch -------------------------------------------
extern "C" void kernel_launch(void* const* d_in, const int* in_sizes, int n_in,
                              void* d_out, int out_size)
{
    const float* t  = (const float*)d_in[0];
    const float* f  = (const float*)d_in[1];
    const void*  mt = d_in[2];
    const void*  mf = d_in[3];
    const float* w  = (const float*)d_in[4];
    float* out = (float*)d_out;

    detect_kernel<<<1, 32>>>((const unsigned int*)mt);
    prep_kernel<<<(Bb * LL + 255) / 256, 256>>>(mt, mf);
    transpose_w<<<dim3(16, 16), dim3(32, 8)>>>(w);
    mma_gemm<0><<<dim3(4, 4, Bb), 256>>>(t, nullptr);
    mma_gemm<1><<<dim3(4, 4, Bb), 256>>>(nullptr, f);
    softmax_kernel<<<2 * Bb, 256>>>();
    combine_kernel<<<dim3(4, Bb), 128>>>(t, f, out);
}

// round 5
// speedup vs baseline: 1.5480x; 1.5480x over previous
#include <cuda_runtime.h>
#include <math.h>
#include <stdint.h>

#define Bb 64
#define LL 512
#define DD 512

// ----------------------------- scratch ---------------------------------------
__device__ float g_proj[(size_t)Bb * LL * DD];   // 64 MB
__device__ float g_wt[DD * DD];                  // W^T (k-major rows)
__device__ float g_mt[Bb * LL];
__device__ float g_mf[Bb * LL];
__device__ float g_rowmax[Bb * LL];
__device__ float g_colmax[Bb * LL];
__device__ float g_alpha_t[Bb * LL];
__device__ float g_alpha_f[Bb * LL];
__device__ int   g_mask_fmt;

// ----------------------------- helpers ---------------------------------------
__device__ __forceinline__ uint32_t bf16x2_pack(float lo, float hi) {
    uint32_t r;
    asm("cvt.rn.bf16x2.f32 %0, %1, %2;" : "=r"(r) : "f"(hi), "f"(lo));
    return r;
}

__device__ __forceinline__ void mma_bf16(float* c, const uint32_t* a, const uint32_t* b) {
    asm volatile(
        "mma.sync.aligned.m16n8k16.row.col.f32.bf16.bf16.f32 "
        "{%0,%1,%2,%3}, {%4,%5,%6,%7}, {%8,%9}, {%0,%1,%2,%3};\n"
        : "+f"(c[0]), "+f"(c[1]), "+f"(c[2]), "+f"(c[3])
        : "r"(a[0]), "r"(a[1]), "r"(a[2]), "r"(a[3]), "r"(b[0]), "r"(b[1]));
}

__device__ __forceinline__ void atomicMaxF(float* a, float v) {
    if (v >= 0.0f) atomicMax((int*)a, __float_as_int(v));
    else           atomicMin((unsigned int*)a, __float_as_uint(v));
}

__device__ __forceinline__ float load_mask(const void* p, int i, int fmt) {
    if (fmt == 0) return ((const int*)p)[i] ? 1.0f : 0.0f;
    if (fmt == 1) return ((const float*)p)[i];
    return ((const unsigned char*)p)[i] ? 1.0f : 0.0f;
}

// ---- bf16 fragment-layout staging ---------------------------------------------
// mma.m16n8k16 A frag (per lane l): a0=(row=l>>2, kp=l&3) a1=(row+8, kp)
//                                   a2=(row, kp+4)        a3=(row+8, kp+4)
//   word index s = ((row&15)>>3) + 2*(kp>=4); lane=(row&7)*4+(kp&3); phys=lane^(lane>>3)
//   As word addr: ((row>>4)*2 + kk)*128 + phys*4 + s      (kk = k16-chunk within BK=32)
// B frag: b0=(col=l>>2, kp=l&3), b1=(col, kp+4); s=(kp>=4)
//   Bs word addr: ((col>>3)*2 + kk)*64 + phys*2 + s
__device__ __forceinline__ void stA_bf(uint32_t* dst, int row, int kk, int p0,
                                       float4 v, float m) {
    uint32_t w0 = bf16x2_pack(v.x * m, v.y * m);
    uint32_t w1 = bf16x2_pack(v.z * m, v.w * m);
    const int base = (((row >> 4) * 2 + kk) << 7) + ((row & 15) >> 3);
    const int rl = (row & 7) * 4;
    int p = p0;
    int lane = rl + (p & 3), phys = lane ^ (lane >> 3);
    dst[base + phys * 4 + ((p >> 2) << 1)] = w0;
    p = p0 + 1;
    lane = rl + (p & 3); phys = lane ^ (lane >> 3);
    dst[base + phys * 4 + ((p >> 2) << 1)] = w1;
}

__device__ __forceinline__ void stB_bf(uint32_t* dst, int col, int kk, int p0,
                                       float4 v, float m) {
    uint32_t w0 = bf16x2_pack(v.x * m, v.y * m);
    uint32_t w1 = bf16x2_pack(v.z * m, v.w * m);
    const int base = (((col >> 3) * 2 + kk) << 6);
    const int rl = (col & 7) * 4;
    int p = p0;
    int lane = rl + (p & 3), phys = lane ^ (lane >> 3);
    dst[base + phys * 2 + (p >> 2)] = w0;
    p = p0 + 1;
    lane = rl + (p & 3); phys = lane ^ (lane >> 3);
    dst[base + phys * 2 + (p >> 2)] = w1;
}

// ----------------------------- small kernels ----------------------------------
__global__ void detect_kernel(const unsigned int* m) {
    int lane = threadIdx.x;
    bool i32 = true, f32 = true;
    for (int i = lane; i < 256; i += 32) {
        unsigned int w = m[i];
        i32 = i32 && (w <= 1u);
        f32 = f32 && (w == 0u || w == 0x3F800000u);
    }
    i32 = __all_sync(0xffffffffu, i32);
    f32 = __all_sync(0xffffffffu, f32);
    if (lane == 0) g_mask_fmt = i32 ? 0 : (f32 ? 1 : 2);
}

__global__ void prep_kernel(const void* mt, const void* mf) {
    int i = blockIdx.x * blockDim.x + threadIdx.x;
    if (i >= Bb * LL) return;
    int fmt = g_mask_fmt;
    g_mt[i] = load_mask(mt, i, fmt);
    g_mf[i] = load_mask(mf, i, fmt);
    float ninf = __int_as_float(0xff800000);
    g_rowmax[i] = ninf;
    g_colmax[i] = ninf;
}

__global__ void transpose_w(const float* __restrict__ W) {
    __shared__ float tile[32][33];
    int tx = threadIdx.x, ty = threadIdx.y;
    int x = blockIdx.x * 32 + tx;
    int y0 = blockIdx.y * 32;
#pragma unroll
    for (int j = 0; j < 32; j += 8)
        tile[ty + j][tx] = W[(size_t)(y0 + ty + j) * DD + x];
    __syncthreads();
    int xo = y0 + tx;
    int yo0 = blockIdx.x * 32;
#pragma unroll
    for (int j = 0; j < 32; j += 8)
        g_wt[(size_t)(yo0 + ty + j) * DD + xo] = tile[tx][ty + j];
}

// ----------------------------- bf16 mma GEMM -----------------------------------
// Both modes compute D[l,n] = sum_k A[l,k] * B[n,k]   (NT form)
// MODE 0: A = t (masked rows m_t), B = g_wt            -> g_proj
// MODE 1: A = g_proj,              B = f (masked m_f)  -> fused row/col max
#define BK 32

template <int MODE>
__global__ void __launch_bounds__(256, 2) mma_gemm(const float* __restrict__ Ag,
                                                   const float* __restrict__ Bg)
{
    __shared__ __align__(16) uint32_t As[2][2048];   // 8 KB per buffer
    __shared__ __align__(16) uint32_t Bs[2][2048];
    __shared__ float s_rmax[128];
    __shared__ float s_cmax[128];

    const int tid  = threadIdx.x;
    const int lane = tid & 31;
    const int wid  = tid >> 5;
    const int wm   = wid & 1;     // 2 warps in M
    const int wn   = wid >> 1;    // 4 warps in N
    const int b  = blockIdx.z;
    const int l0 = blockIdx.y * 128;
    const int n0 = blockIdx.x * 128;

    const float* Aptr;
    const float* Bptr;
    float ma0 = 1.f, ma1 = 1.f, mb0 = 1.f, mb1 = 1.f;

    const int gr = tid >> 2;        // 0..63
    const int gc = (tid & 3) * 4;   // 0,4,8,12 (k offset within 16-k chunk)
    const int p0 = gc >> 1;         // kpair index 0,2,4,6

    if (MODE == 0) {
        Aptr = Ag + (size_t)b * LL * DD;
        Bptr = g_wt;
        ma0 = g_mt[b * LL + l0 + gr];
        ma1 = g_mt[b * LL + l0 + gr + 64];
    } else {
        Aptr = g_proj + (size_t)b * LL * DD;
        Bptr = Bg + (size_t)b * LL * DD;
        mb0 = g_mf[b * LL + n0 + gr];
        mb1 = g_mf[b * LL + n0 + gr + 64];
    }

    if (MODE == 1 && tid < 128) {
        s_rmax[tid] = __int_as_float(0xff800000);
        s_cmax[tid] = __int_as_float(0xff800000);
    }

    const float* Ab0 = Aptr + (size_t)(l0 + gr) * DD + gc;
    const float* Ab1 = Aptr + (size_t)(l0 + gr + 64) * DD + gc;
    const float* Bb0 = Bptr + (size_t)(n0 + gr) * DD + gc;
    const float* Bb1 = Bptr + (size_t)(n0 + gr + 64) * DD + gc;

    float acc[4][4][4];
#pragma unroll
    for (int i = 0; i < 4; i++)
#pragma unroll
        for (int j = 0; j < 4; j++)
#pragma unroll
            for (int q = 0; q < 4; q++) acc[i][j][q] = 0.0f;

    // ---- prologue: stage k-chunk 0 (k 0..31) into buf 0
    {
        float4 v;
        v = *(const float4*)(Ab0);       stA_bf(As[0], gr,      0, p0, v, ma0);
        v = *(const float4*)(Ab0 + 16);  stA_bf(As[0], gr,      1, p0, v, ma0);
        v = *(const float4*)(Ab1);       stA_bf(As[0], gr + 64, 0, p0, v, ma1);
        v = *(const float4*)(Ab1 + 16);  stA_bf(As[0], gr + 64, 1, p0, v, ma1);
        v = *(const float4*)(Bb0);       stB_bf(Bs[0], gr,      0, p0, v, mb0);
        v = *(const float4*)(Bb0 + 16);  stB_bf(Bs[0], gr,      1, p0, v, mb0);
        v = *(const float4*)(Bb1);       stB_bf(Bs[0], gr + 64, 0, p0, v, mb1);
        v = *(const float4*)(Bb1 + 16);  stB_bf(Bs[0], gr + 64, 1, p0, v, mb1);
    }
    __syncthreads();

    const int physL = lane ^ (lane >> 3);
    const int NKT = DD / BK;   // 16
    for (int kt = 0; kt < NKT; kt++) {
        const int buf = kt & 1;
        const int nb  = buf ^ 1;
        const bool more = (kt + 1 < NKT);
        const int K0 = (kt + 1) * BK;

        // prefetch A (next chunk) — 16 regs
        float4 va0, va1, va2, va3;
        if (more) {
            va0 = *(const float4*)(Ab0 + K0);
            va1 = *(const float4*)(Ab0 + K0 + 16);
            va2 = *(const float4*)(Ab1 + K0);
            va3 = *(const float4*)(Ab1 + K0 + 16);
        }

        // ---- kk = 0 MMAs
        {
            uint4 af[4]; uint2 bfv[4];
#pragma unroll
            for (int mt = 0; mt < 4; mt++)
                af[mt] = *(const uint4*)&As[buf][(((wm * 4 + mt) * 2 + 0) << 7) + physL * 4];
#pragma unroll
            for (int nt = 0; nt < 4; nt++)
                bfv[nt] = *(const uint2*)&Bs[buf][(((wn * 4 + nt) * 2 + 0) << 6) + physL * 2];
#pragma unroll
            for (int mt = 0; mt < 4; mt++)
#pragma unroll
                for (int nt = 0; nt < 4; nt++)
                    mma_bf16(acc[mt][nt], (const uint32_t*)&af[mt], (const uint32_t*)&bfv[nt]);
        }

        if (more) {
            stA_bf(As[nb], gr,      0, p0, va0, ma0);
            stA_bf(As[nb], gr,      1, p0, va1, ma0);
            stA_bf(As[nb], gr + 64, 0, p0, va2, ma1);
            stA_bf(As[nb], gr + 64, 1, p0, va3, ma1);
        }

        // prefetch B (next chunk)
        float4 vb0, vb1, vb2, vb3;
        if (more) {
            vb0 = *(const float4*)(Bb0 + K0);
            vb1 = *(const float4*)(Bb0 + K0 + 16);
            vb2 = *(const float4*)(Bb1 + K0);
            vb3 = *(const float4*)(Bb1 + K0 + 16);
        }

        // ---- kk = 1 MMAs
        {
            uint4 af[4]; uint2 bfv[4];
#pragma unroll
            for (int mt = 0; mt < 4; mt++)
                af[mt] = *(const uint4*)&As[buf][(((wm * 4 + mt) * 2 + 1) << 7) + physL * 4];
#pragma unroll
            for (int nt = 0; nt < 4; nt++)
                bfv[nt] = *(const uint2*)&Bs[buf][(((wn * 4 + nt) * 2 + 1) << 6) + physL * 2];
#pragma unroll
            for (int mt = 0; mt < 4; mt++)
#pragma unroll
                for (int nt = 0; nt < 4; nt++)
                    mma_bf16(acc[mt][nt], (const uint32_t*)&af[mt], (const uint32_t*)&bfv[nt]);
        }

        if (more) {
            stB_bf(Bs[nb], gr,      0, p0, vb0, mb0);
            stB_bf(Bs[nb], gr,      1, p0, vb1, mb0);
            stB_bf(Bs[nb], gr + 64, 0, p0, vb2, mb1);
            stB_bf(Bs[nb], gr + 64, 1, p0, vb3, mb1);
            __syncthreads();
        }
    }

    // ----------------------------- epilogue -------------------------------------
    if (MODE == 0) {
        float* Crow = g_proj + (size_t)b * LL * DD;
#pragma unroll
        for (int mt = 0; mt < 4; mt++) {
            const int r = l0 + wm * 64 + mt * 16 + (lane >> 2);
#pragma unroll
            for (int nt = 0; nt < 4; nt++) {
                const int c = n0 + wn * 32 + nt * 8 + 2 * (lane & 3);
                *(float2*)(Crow + (size_t)r * DD + c)       = make_float2(acc[mt][nt][0], acc[mt][nt][1]);
                *(float2*)(Crow + (size_t)(r + 8) * DD + c) = make_float2(acc[mt][nt][2], acc[mt][nt][3]);
            }
        }
    } else {
        __syncthreads();
        const float NINF = __int_as_float(0xff800000);
#pragma unroll
        for (int mt = 0; mt < 4; mt++) {
#pragma unroll
            for (int h = 0; h < 2; h++) {
                float v = NINF;
#pragma unroll
                for (int nt = 0; nt < 4; nt++)
                    v = fmaxf(v, fmaxf(acc[mt][nt][2 * h], acc[mt][nt][2 * h + 1]));
                v = fmaxf(v, __shfl_xor_sync(0xffffffffu, v, 1));
                v = fmaxf(v, __shfl_xor_sync(0xffffffffu, v, 2));
                if ((lane & 3) == 0) {
                    int row = wm * 64 + mt * 16 + (lane >> 2) + h * 8;
                    atomicMaxF(&s_rmax[row], v);
                }
            }
        }
#pragma unroll
        for (int nt = 0; nt < 4; nt++) {
#pragma unroll
            for (int j = 0; j < 2; j++) {
                float v = NINF;
#pragma unroll
                for (int mt = 0; mt < 4; mt++)
                    v = fmaxf(v, fmaxf(acc[mt][nt][j], acc[mt][nt][2 + j]));
                v = fmaxf(v, __shfl_xor_sync(0xffffffffu, v, 4));
                v = fmaxf(v, __shfl_xor_sync(0xffffffffu, v, 8));
                v = fmaxf(v, __shfl_xor_sync(0xffffffffu, v, 16));
                if (lane < 4) {
                    int col = wn * 32 + nt * 8 + 2 * lane + j;
                    atomicMaxF(&s_cmax[col], v);
                }
            }
        }
        __syncthreads();
        if (tid < 128) {
            atomicMaxF(&g_rowmax[b * LL + l0 + tid], s_rmax[tid]);
            atomicMaxF(&g_colmax[b * LL + n0 + tid], s_cmax[tid]);
        }
    }
}

// ----------------------------- softmax ----------------------------------------
__global__ void softmax_kernel() {
    const int idx = blockIdx.x;
    const bool isF = idx >= Bb;
    const int b = isF ? idx - Bb : idx;
    const float* mx = isF ? (g_colmax + b * LL) : (g_rowmax + b * LL);
    const float* mk = isF ? (g_mf + b * LL) : (g_mt + b * LL);
    float* out = isF ? (g_alpha_f + b * LL) : (g_alpha_t + b * LL);

    const int tid = threadIdx.x;
    int i0 = tid, i1 = tid + 256;
    float m0v = mk[i0], m1v = mk[i1];
    float v0 = tanhf(mx[i0]) + (m0v - 1.0f) * 1000000.0f;
    float v1 = tanhf(mx[i1]) + (m1v - 1.0f) * 1000000.0f;

    __shared__ float red[256];
    red[tid] = fmaxf(v0, v1);
    __syncthreads();
    for (int s = 128; s > 0; s >>= 1) {
        if (tid < s) red[tid] = fmaxf(red[tid], red[tid + s]);
        __syncthreads();
    }
    float vm = red[0];
    __syncthreads();

    float e0 = expf(v0 - vm);
    float e1 = expf(v1 - vm);
    red[tid] = e0 + e1;
    __syncthreads();
    for (int s = 128; s > 0; s >>= 1) {
        if (tid < s) red[tid] += red[tid + s];
        __syncthreads();
    }
    float inv = 1.0f / red[0];
    out[i0] = e0 * inv * m0v;
    out[i1] = e1 * inv * m1v;
}

// ----------------------------- combine -----------------------------------------
// grid (4, Bb), block 512: 4 L-chunks of 128 per (b, d-group), smem reduce.
__global__ void combine_kernel(const float* __restrict__ T,
                               const float* __restrict__ F,
                               float* __restrict__ out)
{
    __shared__ float red[512];
    const int b = blockIdx.y;
    const int dl = threadIdx.x & 127;
    const int chunk = threadIdx.x >> 7;           // 0..3
    const int d = blockIdx.x * 128 + dl;
    const float* at = g_alpha_t + b * LL;
    const float* af = g_alpha_f + b * LL;
    const float* tp = T + (size_t)b * LL * DD + d;
    const float* fp = F + (size_t)b * LL * DD + d;
    const int lb = chunk * 128;

    float a0 = 0.f, a1 = 0.f, a2 = 0.f, a3 = 0.f;
    float c0 = 0.f, c1 = 0.f, c2 = 0.f, c3 = 0.f;
#pragma unroll 2
    for (int l = lb; l < lb + 128; l += 8) {
        a0 = fmaf(at[l + 0], tp[(size_t)(l + 0) * DD], a0);
        a1 = fmaf(at[l + 1], tp[(size_t)(l + 1) * DD], a1);
        a2 = fmaf(at[l + 2], tp[(size_t)(l + 2) * DD], a2);
        a3 = fmaf(at[l + 3], tp[(size_t)(l + 3) * DD], a3);
        c0 = fmaf(at[l + 4], tp[(size_t)(l + 4) * DD], c0);
        c1 = fmaf(at[l + 5], tp[(size_t)(l + 5) * DD], c1);
        c2 = fmaf(at[l + 6], tp[(size_t)(l + 6) * DD], c2);
        c3 = fmaf(at[l + 7], tp[(size_t)(l + 7) * DD], c3);
    }
#pragma unroll 2
    for (int m = lb; m < lb + 128; m += 8) {
        a0 = fmaf(af[m + 0], fp[(size_t)(m + 0) * DD], a0);
        a1 = fmaf(af[m + 1], fp[(size_t)(m + 1) * DD], a1);
        a2 = fmaf(af[m + 2], fp[(size_t)(m + 2) * DD], a2);
        a3 = fmaf(af[m + 3], fp[(size_t)(m + 3) * DD], a3);
        c0 = fmaf(af[m + 4], fp[(size_t)(m + 4) * DD], c0);
        c1 = fmaf(af[m + 5], fp[(size_t)(m + 5) * DD], c1);
        c2 = fmaf(af[m + 6], fp[(size_t)(m + 6) * DD], c2);
        c3 = fmaf(af[m + 7], fp[(size_t)(m + 7) * DD], c3);
    }
    red[threadIdx.x] = ((a0 + a1) + (a2 + a3)) + ((c0 + c1) + (c2 + c3));
    __syncthreads();
    if (chunk == 0)
        out[b * DD + d] = (red[dl] + red[dl + 128]) + (red[dl + 256] + red[dl + 384]);
}

// ----------------------------- launch -------------------------------------------
extern "C" void kernel_launch(void* const* d_in, const int* in_sizes, int n_in,
                              void* d_out, int out_size)
{
    const float* t  = (const float*)d_in[0];
    const float* f  = (const float*)d_in[1];
    const void*  mt = d_in[2];
    const void*  mf = d_in[3];
    const float* w  = (const float*)d_in[4];
    float* out = (float*)d_out;

    detect_kernel<<<1, 32>>>((const unsigned int*)mt);
    prep_kernel<<<(Bb * LL + 255) / 256, 256>>>(mt, mf);
    transpose_w<<<dim3(16, 16), dim3(32, 8)>>>(w);
    mma_gemm<0><<<dim3(4, 4, Bb), 256>>>(t, nullptr);
    mma_gemm<1><<<dim3(4, 4, Bb), 256>>>(nullptr, f);
    softmax_kernel<<<2 * Bb, 256>>>();
    combine_kernel<<<dim3(4, Bb), 512>>>(t, f, out);
}